// round 8
// baseline (speedup 1.0000x reference)
#include <cuda_runtime.h>
#include <math.h>
#include <stdint.h>

#define B 64
#define UNITS 512
#define EMB 256
#define NSENT 32
#define NWORD 50
#define VOCAB 50000
#define OOV 100
#define EXT (VOCAB + OOV)

#define DEC_OFF   0
#define GEN_OFF   (B*UNITS)
#define COPY_OFF  (GEN_OFF + B*EXT)
#define PGEN_OFF  (COPY_OFF + B*EXT)

#define HID_N (B * (UNITS/2))    // 16384

// ---------------- scratch ----------------
__device__ float g_xm[B * 3 * UNITS];
__device__ float g_hm[B * 3 * UNITS];
__device__ float g_q[B * UNITS];
__device__ float g_qw[B * UNITS];
__device__ float g_alpha[B * NSENT];
__device__ float g_xcat[B * 2 * UNITS];
__device__ float g_hpart[8 * HID_N];      // split-K partials (no zeroing needed)
__device__ float g_hidden[HID_N];
__device__ float g_expsum[B];
__device__ float g_sink;

// ============ small GEMM, two fused jobs ============
__global__ __launch_bounds__(256) void gemm_dual_kernel(
    const float* __restrict__ A0, int lda0, const float* __restrict__ B0, int ldb0,
    const float* __restrict__ bias0, float* __restrict__ C0, int ldc0, int K0, int nt0,
    const float* __restrict__ A1, int lda1, const float* __restrict__ B1, int ldb1,
    const float* __restrict__ bias1, float* __restrict__ C1, int ldc1, int K1)
{
    __shared__ float As[32][68];
    __shared__ float Bs[32][32];

    int bx = blockIdx.x;
    const float *A, *Bm, *bias; float* C; int lda, ldb, ldc, K, n0;
    if (bx < nt0) { A=A0; Bm=B0; bias=bias0; C=C0; lda=lda0; ldb=ldb0; ldc=ldc0; K=K0; n0=bx*32; }
    else          { A=A1; Bm=B1; bias=bias1; C=C1; lda=lda1; ldb=ldb1; ldc=ldc1; K=K1; n0=(bx-nt0)*32; }

    int tid = threadIdx.x;
    int tm = tid >> 4, tn = tid & 15;
    float acc[4][2] = {};

    for (int k0 = 0; k0 < K; k0 += 32) {
#pragma unroll
        for (int i = 0; i < 8; i++) {
            int idx = i * 256 + tid;
            int m  = idx >> 5;
            int kk = idx & 31;
            As[kk][m] = A[(size_t)m * lda + k0 + kk];
        }
        {
            int kk = tid >> 3;
            int c  = (tid & 7) * 4;
            *(float4*)&Bs[kk][c] = *(const float4*)(Bm + (size_t)(k0 + kk) * ldb + n0 + c);
        }
        __syncthreads();
#pragma unroll
        for (int k = 0; k < 32; k++) {
            float4 a = *(float4*)&As[k][tm * 4];
            float2 b = *(float2*)&Bs[k][tn * 2];
            acc[0][0] += a.x * b.x; acc[0][1] += a.x * b.y;
            acc[1][0] += a.y * b.x; acc[1][1] += a.y * b.y;
            acc[2][0] += a.z * b.x; acc[2][1] += a.z * b.y;
            acc[3][0] += a.w * b.x; acc[3][1] += a.w * b.y;
        }
        __syncthreads();
    }
#pragma unroll
    for (int jm = 0; jm < 4; jm++) {
        int m = tm * 4 + jm;
#pragma unroll
        for (int jn = 0; jn < 2; jn++) {
            int n = n0 + tn * 2 + jn;
            float v = acc[jm][jn];
            if (bias) v += bias[n];
            C[(size_t)m * ldc + n] = v;
        }
    }
}

// ============ split-K GEMM for weight_dec: partials, no atomics ============
__global__ __launch_bounds__(256) void gemm_splitk_kernel(
    const float* __restrict__ A, int lda, const float* __restrict__ Bm, int ldb,
    int ksplit)
{
    __shared__ float As[32][68];
    __shared__ float Bs[32][32];
    int tid = threadIdx.x;
    int tm = tid >> 4, tn = tid & 15;
    int n0 = blockIdx.x * 32;
    int kbase = blockIdx.y * ksplit;
    float* C = g_hpart + (size_t)blockIdx.y * HID_N;

    float acc[4][2] = {};
    for (int kc = 0; kc < ksplit; kc += 32) {
        int k0 = kbase + kc;
#pragma unroll
        for (int i = 0; i < 8; i++) {
            int idx = i * 256 + tid;
            int m  = idx >> 5;
            int kk = idx & 31;
            As[kk][m] = A[(size_t)m * lda + k0 + kk];
        }
        {
            int kk = tid >> 3;
            int c  = (tid & 7) * 4;
            *(float4*)&Bs[kk][c] = *(const float4*)(Bm + (size_t)(k0 + kk) * ldb + n0 + c);
        }
        __syncthreads();
#pragma unroll
        for (int k = 0; k < 32; k++) {
            float4 a = *(float4*)&As[k][tm * 4];
            float2 b = *(float2*)&Bs[k][tn * 2];
            acc[0][0] += a.x * b.x; acc[0][1] += a.x * b.y;
            acc[1][0] += a.y * b.x; acc[1][1] += a.y * b.y;
            acc[2][0] += a.z * b.x; acc[2][1] += a.z * b.y;
            acc[3][0] += a.w * b.x; acc[3][1] += a.w * b.y;
        }
        __syncthreads();
    }
#pragma unroll
    for (int jm = 0; jm < 4; jm++) {
        int m = tm * 4 + jm;
#pragma unroll
        for (int jn = 0; jn < 2; jn++)
            C[(size_t)m * (UNITS/2) + n0 + tn * 2 + jn] = acc[jm][jn];
    }
}

// sum partials + tanh; also zero expsum (runs before fc on same stream)
__global__ void tanh_kernel() {
    int i = blockIdx.x * blockDim.x + threadIdx.x;
    if (i < HID_N) {
        float s = 0.f;
#pragma unroll
        for (int p = 0; p < 8; p++) s += g_hpart[p * HID_N + i];
        g_hidden[i] = tanhf(s);
    }
    if (i < B) g_expsum[i] = 0.f;
}

// ============ L2 warm for fcW ============
__global__ void warm_kernel(const float4* __restrict__ w, int n4) {
    float s = 0.f;
    for (size_t i = blockIdx.x * blockDim.x + threadIdx.x; i < (size_t)n4;
         i += (size_t)gridDim.x * blockDim.x) {
        float4 v = w[i];
        s += v.x + v.y + v.z + v.w;
    }
    if (s == 1.234567e30f) g_sink = s;   // unreachable; defeats DCE
}

// ============ fc GEMM: tf32 mma.sync m16n8k8 (unchanged from R7) ============
#define FC_A_FLOATS  (64 * 260)
#define FC_B_FLOATS  (2 * 32 * 136)
#define FC_SMEM      ((FC_A_FLOATS + FC_B_FLOATS + 64) * 4)

__device__ __forceinline__ uint32_t f2tf32(float f) {
    uint32_t t;
    asm("cvt.rna.tf32.f32 %0, %1;" : "=r"(t) : "f"(f));
    return t;
}

__global__ __launch_bounds__(256) void fc_gemm_kernel(
    const float* __restrict__ Bm,
    const float* __restrict__ bias,
    float* __restrict__ out)
{
    extern __shared__ float sm[];
    uint32_t* As  = (uint32_t*)sm;
    uint32_t* Bs  = (uint32_t*)(sm + FC_A_FLOATS);
    float*    red = sm + FC_A_FLOATS + FC_B_FLOATS;

    int tid  = threadIdx.x;
    int lane = tid & 31;
    int w    = tid >> 5;
    int m0   = (w & 3) * 16;
    int n0w  = (w >> 2) * 64;
    int n0   = blockIdx.x * 128;
    int r    = lane >> 2;
    int cq   = lane & 3;

    if (tid < 64) red[tid] = 0.f;

#pragma unroll 4
    for (int i = 0; i < 64; i++) {
        int idx = i * 256 + tid;
        int m = idx >> 8, k = idx & 255;
        As[m * 260 + k] = f2tf32(g_hidden[idx]);
    }

    float c[8][4];
#pragma unroll
    for (int i = 0; i < 8; i++)
#pragma unroll
        for (int j = 0; j < 4; j++) c[i][j] = 0.f;

    float4 bregs[4];

#define LDG_B(c0) do { \
    _Pragma("unroll") \
    for (int i = 0; i < 4; i++) { \
        int v = i * 256 + tid; int kk = v >> 5, cc = (v & 31) * 4; int n = n0 + cc; \
        bregs[i] = (n + 3 < VOCAB) \
            ? *(const float4*)(Bm + (size_t)((c0) + kk) * VOCAB + n) \
            : make_float4(0.f, 0.f, 0.f, 0.f); \
    } } while (0)

#define STS_B(buf) do { \
    _Pragma("unroll") \
    for (int i = 0; i < 4; i++) { \
        int v = i * 256 + tid; int kk = v >> 5, cc = (v & 31) * 4; \
        uint32_t* p = Bs + (buf) * 4352 + kk * 136 + cc; \
        p[0] = f2tf32(bregs[i].x); p[1] = f2tf32(bregs[i].y); \
        p[2] = f2tf32(bregs[i].z); p[3] = f2tf32(bregs[i].w); \
    } } while (0)

    LDG_B(0);
    STS_B(0);
    __syncthreads();

#pragma unroll 1
    for (int ch = 0; ch < 8; ch++) {
        int cur = ch & 1, nxt = cur ^ 1;
        if (ch < 7) LDG_B((ch + 1) * 32);

        const uint32_t* Bb = Bs + cur * 4352;
#pragma unroll
        for (int k8 = 0; k8 < 4; k8++) {
            int gk = ch * 32 + k8 * 8;
            uint32_t a0 = As[(m0 + r)     * 260 + gk + cq];
            uint32_t a1 = As[(m0 + r + 8) * 260 + gk + cq];
            uint32_t a2 = As[(m0 + r)     * 260 + gk + cq + 4];
            uint32_t a3 = As[(m0 + r + 8) * 260 + gk + cq + 4];
            const uint32_t* brow0 = Bb + (k8 * 8 + cq) * 136;
            const uint32_t* brow1 = brow0 + 4 * 136;
#pragma unroll
            for (int nt = 0; nt < 8; nt++) {
                uint32_t b0 = brow0[n0w + nt * 8 + r];
                uint32_t b1 = brow1[n0w + nt * 8 + r];
                asm volatile(
                    "mma.sync.aligned.m16n8k8.row.col.f32.tf32.tf32.f32 "
                    "{%0,%1,%2,%3}, {%4,%5,%6,%7}, {%8,%9}, {%0,%1,%2,%3};"
                    : "+f"(c[nt][0]), "+f"(c[nt][1]), "+f"(c[nt][2]), "+f"(c[nt][3])
                    : "r"(a0), "r"(a1), "r"(a2), "r"(a3), "r"(b0), "r"(b1));
            }
        }
        if (ch < 7) STS_B(nxt);
        __syncthreads();
    }

    int row_lo = m0 + r;
    int row_hi = row_lo + 8;
    float sum_lo = 0.f, sum_hi = 0.f;
#pragma unroll
    for (int nt = 0; nt < 8; nt++) {
        int ncol = n0 + n0w + nt * 8 + cq * 2;
        if (ncol + 1 < VOCAB) {
            float e0 = __expf(c[nt][0] + bias[ncol]);
            float e1 = __expf(c[nt][1] + bias[ncol + 1]);
            float e2 = __expf(c[nt][2] + bias[ncol]);
            float e3 = __expf(c[nt][3] + bias[ncol + 1]);
            *(float2*)&out[GEN_OFF + (size_t)row_lo * EXT + ncol] = make_float2(e0, e1);
            *(float2*)&out[GEN_OFF + (size_t)row_hi * EXT + ncol] = make_float2(e2, e3);
            sum_lo += e0 + e1;
            sum_hi += e2 + e3;
        } else if (ncol < VOCAB) {
            float e0 = __expf(c[nt][0] + bias[ncol]);
            float e2 = __expf(c[nt][2] + bias[ncol]);
            out[GEN_OFF + (size_t)row_lo * EXT + ncol] = e0;
            out[GEN_OFF + (size_t)row_hi * EXT + ncol] = e2;
            sum_lo += e0;
            sum_hi += e2;
        }
    }
    atomicAdd(&red[row_lo], sum_lo);
    atomicAdd(&red[row_hi], sum_hi);
    __syncthreads();
    if (tid < 64) atomicAdd(&g_expsum[tid], red[tid]);
}

__global__ void normalize_kernel(float* __restrict__ out) {
    int idx = blockIdx.x * blockDim.x + threadIdx.x;
    if (idx >= B * EXT) return;
    int b = idx / EXT;
    int v = idx - b * EXT;
    float* p = out + GEN_OFF + idx;
    *p = (v < VOCAB) ? (*p) * (1.f / g_expsum[b]) : 0.f;
}

// ---------------- GRU gate ----------------
__global__ void gru_gate_kernel(const float* __restrict__ hprev, float* __restrict__ out) {
    int idx = blockIdx.x * blockDim.x + threadIdx.x;
    if (idx >= B * UNITS) return;
    int b = idx >> 9, u = idx & 511;
    const float* xm = g_xm + b * (3 * UNITS);
    const float* hm = g_hm + b * (3 * UNITS);
    float z  = 1.f / (1.f + __expf(-(xm[u] + hm[u])));
    float r  = 1.f / (1.f + __expf(-(xm[UNITS + u] + hm[UNITS + u])));
    float hc = tanhf(xm[2 * UNITS + u] + r * hm[2 * UNITS + u]);
    float h  = hprev[idx];
    float hn = z * h + (1.f - z) * hc;
    out[DEC_OFF + idx] = hn;
    g_xcat[b * (2 * UNITS) + UNITS + u] = hn;
}

// ---------------- sentence attention ----------------
__global__ __launch_bounds__(512) void attn_sent_kernel(const float* __restrict__ encS) {
    __shared__ float q_s[UNITS];
    __shared__ float sc_s[NSENT];
    __shared__ float alpha_s[NSENT];
    int b = blockIdx.x, tid = threadIdx.x;
    int warp = tid >> 5, lane = tid & 31;

    q_s[tid] = g_q[b * UNITS + tid];
    __syncthreads();
#pragma unroll
    for (int i = 0; i < 2; i++) {
        int s = warp * 2 + i;
        const float4* row = (const float4*)(encS + ((size_t)(b * NSENT + s)) * UNITS);
        const float4* qv  = (const float4*)q_s;
        float acc = 0.f;
#pragma unroll
        for (int t = 0; t < 4; t++) {
            float4 e = row[lane + t * 32], qq = qv[lane + t * 32];
            acc += e.x*qq.x + e.y*qq.y + e.z*qq.z + e.w*qq.w;
        }
#pragma unroll
        for (int o = 16; o > 0; o >>= 1) acc += __shfl_down_sync(0xffffffffu, acc, o);
        if (lane == 0) sc_s[s] = acc;
    }
    __syncthreads();
    if (warp == 0) {
        float x = sc_s[lane], m = x;
#pragma unroll
        for (int o = 16; o > 0; o >>= 1) m = fmaxf(m, __shfl_xor_sync(0xffffffffu, m, o));
        float e = __expf(x - m), s = e;
#pragma unroll
        for (int o = 16; o > 0; o >>= 1) s += __shfl_xor_sync(0xffffffffu, s, o);
        float a = e / s;
        alpha_s[lane] = a;
        g_alpha[b * NSENT + lane] = a;
    }
    __syncthreads();
    {
        float c = 0.f;
#pragma unroll
        for (int s = 0; s < NSENT; s++)
            c += alpha_s[s] * encS[((size_t)(b * NSENT + s)) * UNITS + tid];
        g_xcat[b * (2 * UNITS) + tid] = c;
    }
}

// ---------------- word attention + scatter + fused pgen ----------------
__global__ __launch_bounds__(256) void word_attn_scatter_kernel(
    const float* __restrict__ encW, const int* __restrict__ numeric,
    const float* __restrict__ emb, const float* __restrict__ wc,
    const float* __restrict__ wh, const float* __restrict__ wi,
    float* __restrict__ out)
{
    __shared__ float qw_s[UNITS];
    __shared__ float sc_s[NWORD];
    __shared__ float ms_s[2];
    int bid = blockIdx.x;
    int tid = threadIdx.x, warp = tid >> 5, lane = tid & 31;

    if (bid >= B * NSENT) {
        // ---- pgen block ----
        int b = bid - B * NSENT;
        const float* ctx = g_xcat + b * (2 * UNITS);
        const float* dec = ctx + UNITS;
        float acc = 0.f;
        for (int k = tid; k < UNITS; k += 256) {
            acc += ctx[k] * wc[k] + dec[k] * wh[k];
            if (k < EMB) acc += emb[b * EMB + k] * wi[k];
        }
        qw_s[tid] = acc;
        __syncthreads();
        for (int o = 128; o > 0; o >>= 1) {
            if (tid < o) qw_s[tid] += qw_s[tid + o];
            __syncthreads();
        }
        if (tid == 0) out[PGEN_OFF + b] = 1.f / (1.f + __expf(-qw_s[0]));
        return;
    }

    int b = bid >> 5, s = bid & 31;
    for (int u = tid; u < UNITS; u += 256) qw_s[u] = g_qw[b * UNITS + u];
    __syncthreads();
    const float* base = encW + ((size_t)(b * NSENT + s)) * NWORD * UNITS;
    for (int w = warp; w < NWORD; w += 8) {
        const float4* row = (const float4*)(base + (size_t)w * UNITS);
        const float4* qv  = (const float4*)qw_s;
        float acc = 0.f;
#pragma unroll
        for (int t = 0; t < 4; t++) {
            float4 e = __ldcs(&row[lane + t * 32]);   // evict-first: don't pollute L2
            float4 qq = qv[lane + t * 32];
            acc += e.x*qq.x + e.y*qq.y + e.z*qq.z + e.w*qq.w;
        }
#pragma unroll
        for (int o = 16; o > 0; o >>= 1) acc += __shfl_down_sync(0xffffffffu, acc, o);
        if (lane == 0) sc_s[w] = acc;
    }
    __syncthreads();
    if (warp == 0) {
        float m = -1e30f;
        for (int i = lane; i < NWORD; i += 32) m = fmaxf(m, sc_s[i]);
#pragma unroll
        for (int o = 16; o > 0; o >>= 1) m = fmaxf(m, __shfl_xor_sync(0xffffffffu, m, o));
        float ssum = 0.f;
        for (int i = lane; i < NWORD; i += 32) ssum += __expf(sc_s[i] - m);
#pragma unroll
        for (int o = 16; o > 0; o >>= 1) ssum += __shfl_xor_sync(0xffffffffu, ssum, o);
        if (lane == 0) { ms_s[0] = m; ms_s[1] = ssum; }
    }
    __syncthreads();
    if (tid < NWORD) {
        float alpha = g_alpha[b * NSENT + s];
        float v = alpha * __expf(sc_s[tid] - ms_s[0]) / ms_s[1];
        int col = numeric[b * (NSENT * NWORD) + s * NWORD + tid];
        atomicAdd(&out[COPY_OFF + (size_t)b * EXT + col], v);
    }
}

// ---------------- launch ----------------
extern "C" void kernel_launch(void* const* d_in, const int* in_sizes, int n_in,
                              void* d_out, int out_size)
{
    const float* emb   = (const float*)d_in[0];
    const float* hid   = (const float*)d_in[1];
    const float* encS  = (const float*)d_in[2];
    const float* encW  = (const float*)d_in[3];
    const int*   numr  = (const int*)d_in[4];
    int o = (in_sizes[5] == 1) ? 6 : 5;
    const float* gruWx = (const float*)d_in[o + 0];
    const float* gruWh = (const float*)d_in[o + 1];
    const float* grub  = (const float*)d_in[o + 2];
    const float* WatS  = (const float*)d_in[o + 3];
    const float* WatW  = (const float*)d_in[o + 4];
    const float* fcW   = (const float*)d_in[o + 5];
    const float* fcb   = (const float*)d_in[o + 6];
    const float* wctx  = (const float*)d_in[o + 7];
    const float* whid  = (const float*)d_in[o + 8];
    const float* wdec  = (const float*)d_in[o + 9];
    const float* winp  = (const float*)d_in[o + 10];

    float* out = (float*)d_out;

    float *xm, *hm, *q, *qw, *xcat;
    cudaGetSymbolAddress((void**)&xm, g_xm);
    cudaGetSymbolAddress((void**)&hm, g_hm);
    cudaGetSymbolAddress((void**)&q,  g_q);
    cudaGetSymbolAddress((void**)&qw, g_qw);
    cudaGetSymbolAddress((void**)&xcat, g_xcat);

    static cudaStream_t s1 = nullptr;
    static cudaEvent_t ev_fork = nullptr, ev_alpha = nullptr, ev_join = nullptr;
    if (!s1) {
        cudaStreamCreateWithFlags(&s1, cudaStreamNonBlocking);
        cudaEventCreateWithFlags(&ev_fork,  cudaEventDisableTiming);
        cudaEventCreateWithFlags(&ev_alpha, cudaEventDisableTiming);
        cudaEventCreateWithFlags(&ev_join,  cudaEventDisableTiming);
        cudaFuncSetAttribute(fc_gemm_kernel,
                             cudaFuncAttributeMaxDynamicSharedMemorySize, FC_SMEM);
    }

    // fork: side stream zeroes copy region + warms fcW in L2 while main chain runs
    cudaEventRecord(ev_fork, 0);
    cudaStreamWaitEvent(s1, ev_fork, 0);
    cudaMemsetAsync(out + COPY_OFF, 0, (size_t)B * EXT * sizeof(float), s1);
    warm_kernel<<<592, 256, 0, s1>>>((const float4*)fcW, (UNITS/2) * VOCAB / 4);

    // main: GRU pre-activations (fused) -> gate -> queries -> sentence attention
    gemm_dual_kernel<<<96, 256>>>(
        emb, EMB, gruWx, 3*UNITS, grub,           xm, 3*UNITS, EMB, 48,
        hid, UNITS, gruWh, 3*UNITS, grub+3*UNITS, hm, 3*UNITS, UNITS);
    gru_gate_kernel<<<(B*UNITS + 255)/256, 256>>>(hid, out);
    gemm_dual_kernel<<<32, 256>>>(
        out + DEC_OFF, UNITS, WatS, UNITS, nullptr, q,  UNITS, UNITS, 16,
        out + DEC_OFF, UNITS, WatW, UNITS, nullptr, qw, UNITS, UNITS);
    attn_sent_kernel<<<B, 512>>>(encS);
    cudaEventRecord(ev_alpha, 0);

    // side: word attention + scatter + pgen (fused)
    cudaStreamWaitEvent(s1, ev_alpha, 0);
    word_attn_scatter_kernel<<<B * NSENT + B, 256, 0, s1>>>(
        encW, numr, emb, wctx, whid, winp, out);
    cudaEventRecord(ev_join, s1);

    // main: hidden (split-K partials) -> tanh+sum (+expsum zero) -> fc -> normalize
    gemm_splitk_kernel<<<dim3(8, 8), 256>>>(xcat, 2*UNITS, wdec, UNITS/2, 128);
    tanh_kernel<<<(HID_N + 255)/256, 256>>>();
    fc_gemm_kernel<<<(VOCAB + 127)/128, 256, FC_SMEM>>>(fcW, fcb, out);
    normalize_kernel<<<(B*EXT + 255)/256, 256>>>(out);

    cudaStreamWaitEvent(0, ev_join, 0);
}

// round 9
// speedup vs baseline: 1.3059x; 1.3059x over previous
#include <cuda_runtime.h>
#include <math.h>
#include <stdint.h>

#define B 64
#define UNITS 512
#define EMB 256
#define NSENT 32
#define NWORD 50
#define VOCAB 50000
#define OOV 100
#define EXT (VOCAB + OOV)

#define DEC_OFF   0
#define GEN_OFF   (B*UNITS)
#define COPY_OFF  (GEN_OFF + B*EXT)
#define PGEN_OFF  (COPY_OFF + B*EXT)

#define HID_N (B * (UNITS/2))    // 16384

// ---------------- scratch ----------------
__device__ float g_xm[B * 3 * UNITS];
__device__ float g_hm[B * 3 * UNITS];
__device__ float g_q[B * UNITS];
__device__ float g_qw[B * UNITS];
__device__ float g_alpha[B * NSENT];
__device__ float g_xcat[B * 2 * UNITS];
__device__ float g_hpart[8 * HID_N];
__device__ float g_hidden[HID_N];
__device__ float g_expsum[B];

// ============ small GEMM, two fused jobs, register-prefetch pipelined ============
__global__ __launch_bounds__(256) void gemm_dual_kernel(
    const float* __restrict__ A0, int lda0, const float* __restrict__ B0, int ldb0,
    const float* __restrict__ bias0, float* __restrict__ C0, int ldc0, int K0, int nt0,
    const float* __restrict__ A1, int lda1, const float* __restrict__ B1, int ldb1,
    const float* __restrict__ bias1, float* __restrict__ C1, int ldc1, int K1)
{
    __shared__ float As[2][32][68];
    __shared__ float Bs[2][32][32];

    int bx = blockIdx.x;
    const float *A, *Bm, *bias; float* C; int lda, ldb, ldc, K, n0;
    if (bx < nt0) { A=A0; Bm=B0; bias=bias0; C=C0; lda=lda0; ldb=ldb0; ldc=ldc0; K=K0; n0=bx*32; }
    else          { A=A1; Bm=B1; bias=bias1; C=C1; lda=lda1; ldb=ldb1; ldc=ldc1; K=K1; n0=(bx-nt0)*32; }

    int tid = threadIdx.x;
    int tm = tid >> 4, tn = tid & 15;
    int la_m = tid >> 5, la_k = tid & 31;          // A-load mapping (8 rounds)
    int lb_k = tid >> 3, lb_c = (tid & 7) * 4;     // B-load mapping
    int nchunks = K >> 5;

    float ar[8]; float4 br;

#define DLDG(c0) do { \
    _Pragma("unroll") \
    for (int i = 0; i < 8; i++) \
        ar[i] = A[(size_t)(i * 8 + la_m) * lda + (c0) + la_k]; \
    br = *(const float4*)(Bm + (size_t)((c0) + lb_k) * ldb + n0 + lb_c); } while (0)

#define DSTS(buf) do { \
    _Pragma("unroll") \
    for (int i = 0; i < 8; i++) As[buf][la_k][i * 8 + la_m] = ar[i]; \
    *(float4*)&Bs[buf][lb_k][lb_c] = br; } while (0)

    float acc[4][2] = {};
    DLDG(0);
    DSTS(0);
    __syncthreads();

    for (int c = 0; c < nchunks; c++) {
        int cur = c & 1, nxt = cur ^ 1;
        if (c + 1 < nchunks) DLDG((c + 1) * 32);
#pragma unroll
        for (int k = 0; k < 32; k++) {
            float4 a = *(float4*)&As[cur][k][tm * 4];
            float2 b = *(float2*)&Bs[cur][k][tn * 2];
            acc[0][0] += a.x * b.x; acc[0][1] += a.x * b.y;
            acc[1][0] += a.y * b.x; acc[1][1] += a.y * b.y;
            acc[2][0] += a.z * b.x; acc[2][1] += a.z * b.y;
            acc[3][0] += a.w * b.x; acc[3][1] += a.w * b.y;
        }
        if (c + 1 < nchunks) DSTS(nxt);
        __syncthreads();
    }
#pragma unroll
    for (int jm = 0; jm < 4; jm++) {
        int m = tm * 4 + jm;
#pragma unroll
        for (int jn = 0; jn < 2; jn++) {
            int n = n0 + tn * 2 + jn;
            float v = acc[jm][jn];
            if (bias) v += bias[n];
            C[(size_t)m * ldc + n] = v;
        }
    }
}

// ============ split-K GEMM for weight_dec: pipelined, partials ============
__global__ __launch_bounds__(256) void gemm_splitk_kernel(
    const float* __restrict__ A, int lda, const float* __restrict__ Bm, int ldb,
    int ksplit)
{
    __shared__ float As[2][32][68];
    __shared__ float Bs[2][32][32];
    int tid = threadIdx.x;
    int tm = tid >> 4, tn = tid & 15;
    int la_m = tid >> 5, la_k = tid & 31;
    int lb_k = tid >> 3, lb_c = (tid & 7) * 4;
    int n0 = blockIdx.x * 32;
    int kbase = blockIdx.y * ksplit;
    int nchunks = ksplit >> 5;
    float* C = g_hpart + (size_t)blockIdx.y * HID_N;

    float ar[8]; float4 br;
    float acc[4][2] = {};

#define SLDG(c0) do { \
    _Pragma("unroll") \
    for (int i = 0; i < 8; i++) \
        ar[i] = A[(size_t)(i * 8 + la_m) * lda + (c0) + la_k]; \
    br = *(const float4*)(Bm + (size_t)((c0) + lb_k) * ldb + n0 + lb_c); } while (0)

    SLDG(kbase);
    {
#pragma unroll
        for (int i = 0; i < 8; i++) As[0][la_k][i * 8 + la_m] = ar[i];
        *(float4*)&Bs[0][lb_k][lb_c] = br;
    }
    __syncthreads();

    for (int c = 0; c < nchunks; c++) {
        int cur = c & 1, nxt = cur ^ 1;
        if (c + 1 < nchunks) SLDG(kbase + (c + 1) * 32);
#pragma unroll
        for (int k = 0; k < 32; k++) {
            float4 a = *(float4*)&As[cur][k][tm * 4];
            float2 b = *(float2*)&Bs[cur][k][tn * 2];
            acc[0][0] += a.x * b.x; acc[0][1] += a.x * b.y;
            acc[1][0] += a.y * b.x; acc[1][1] += a.y * b.y;
            acc[2][0] += a.z * b.x; acc[2][1] += a.z * b.y;
            acc[3][0] += a.w * b.x; acc[3][1] += a.w * b.y;
        }
        if (c + 1 < nchunks) {
#pragma unroll
            for (int i = 0; i < 8; i++) As[nxt][la_k][i * 8 + la_m] = ar[i];
            *(float4*)&Bs[nxt][lb_k][lb_c] = br;
        }
        __syncthreads();
    }
#pragma unroll
    for (int jm = 0; jm < 4; jm++) {
        int m = tm * 4 + jm;
#pragma unroll
        for (int jn = 0; jn < 2; jn++)
            C[(size_t)m * (UNITS/2) + n0 + tn * 2 + jn] = acc[jm][jn];
    }
}

// sum partials + tanh; also zero expsum
__global__ void tanh_kernel() {
    int i = blockIdx.x * blockDim.x + threadIdx.x;
    if (i < HID_N) {
        float s = 0.f;
#pragma unroll
        for (int p = 0; p < 8; p++) s += g_hpart[p * HID_N + i];
        g_hidden[i] = tanhf(s);
    }
    if (i < B) g_expsum[i] = 0.f;
}

// ============ fc GEMM: tf32 mma.sync m16n8k8 (unchanged, proven) ============
#define FC_A_FLOATS  (64 * 260)
#define FC_B_FLOATS  (2 * 32 * 136)
#define FC_SMEM      ((FC_A_FLOATS + FC_B_FLOATS + 64) * 4)

__device__ __forceinline__ uint32_t f2tf32(float f) {
    uint32_t t;
    asm("cvt.rna.tf32.f32 %0, %1;" : "=r"(t) : "f"(f));
    return t;
}

__global__ __launch_bounds__(256) void fc_gemm_kernel(
    const float* __restrict__ Bm,
    const float* __restrict__ bias,
    float* __restrict__ out)
{
    extern __shared__ float sm[];
    uint32_t* As  = (uint32_t*)sm;
    uint32_t* Bs  = (uint32_t*)(sm + FC_A_FLOATS);
    float*    red = sm + FC_A_FLOATS + FC_B_FLOATS;

    int tid  = threadIdx.x;
    int lane = tid & 31;
    int w    = tid >> 5;
    int m0   = (w & 3) * 16;
    int n0w  = (w >> 2) * 64;
    int n0   = blockIdx.x * 128;
    int r    = lane >> 2;
    int cq   = lane & 3;

    if (tid < 64) red[tid] = 0.f;

#pragma unroll 4
    for (int i = 0; i < 64; i++) {
        int idx = i * 256 + tid;
        int m = idx >> 8, k = idx & 255;
        As[m * 260 + k] = f2tf32(g_hidden[idx]);
    }

    float c[8][4];
#pragma unroll
    for (int i = 0; i < 8; i++)
#pragma unroll
        for (int j = 0; j < 4; j++) c[i][j] = 0.f;

    float4 bregs[4];

#define LDG_B(c0) do { \
    _Pragma("unroll") \
    for (int i = 0; i < 4; i++) { \
        int v = i * 256 + tid; int kk = v >> 5, cc = (v & 31) * 4; int n = n0 + cc; \
        bregs[i] = (n + 3 < VOCAB) \
            ? *(const float4*)(Bm + (size_t)((c0) + kk) * VOCAB + n) \
            : make_float4(0.f, 0.f, 0.f, 0.f); \
    } } while (0)

#define STS_B(buf) do { \
    _Pragma("unroll") \
    for (int i = 0; i < 4; i++) { \
        int v = i * 256 + tid; int kk = v >> 5, cc = (v & 31) * 4; \
        uint32_t* p = Bs + (buf) * 4352 + kk * 136 + cc; \
        p[0] = f2tf32(bregs[i].x); p[1] = f2tf32(bregs[i].y); \
        p[2] = f2tf32(bregs[i].z); p[3] = f2tf32(bregs[i].w); \
    } } while (0)

    LDG_B(0);
    STS_B(0);
    __syncthreads();

#pragma unroll 1
    for (int ch = 0; ch < 8; ch++) {
        int cur = ch & 1, nxt = cur ^ 1;
        if (ch < 7) LDG_B((ch + 1) * 32);

        const uint32_t* Bb = Bs + cur * 4352;
#pragma unroll
        for (int k8 = 0; k8 < 4; k8++) {
            int gk = ch * 32 + k8 * 8;
            uint32_t a0 = As[(m0 + r)     * 260 + gk + cq];
            uint32_t a1 = As[(m0 + r + 8) * 260 + gk + cq];
            uint32_t a2 = As[(m0 + r)     * 260 + gk + cq + 4];
            uint32_t a3 = As[(m0 + r + 8) * 260 + gk + cq + 4];
            const uint32_t* brow0 = Bb + (k8 * 8 + cq) * 136;
            const uint32_t* brow1 = brow0 + 4 * 136;
#pragma unroll
            for (int nt = 0; nt < 8; nt++) {
                uint32_t b0 = brow0[n0w + nt * 8 + r];
                uint32_t b1 = brow1[n0w + nt * 8 + r];
                asm volatile(
                    "mma.sync.aligned.m16n8k8.row.col.f32.tf32.tf32.f32 "
                    "{%0,%1,%2,%3}, {%4,%5,%6,%7}, {%8,%9}, {%0,%1,%2,%3};"
                    : "+f"(c[nt][0]), "+f"(c[nt][1]), "+f"(c[nt][2]), "+f"(c[nt][3])
                    : "r"(a0), "r"(a1), "r"(a2), "r"(a3), "r"(b0), "r"(b1));
            }
        }
        if (ch < 7) STS_B(nxt);
        __syncthreads();
    }

    int row_lo = m0 + r;
    int row_hi = row_lo + 8;
    float sum_lo = 0.f, sum_hi = 0.f;
#pragma unroll
    for (int nt = 0; nt < 8; nt++) {
        int ncol = n0 + n0w + nt * 8 + cq * 2;
        if (ncol + 1 < VOCAB) {
            float e0 = __expf(c[nt][0] + bias[ncol]);
            float e1 = __expf(c[nt][1] + bias[ncol + 1]);
            float e2 = __expf(c[nt][2] + bias[ncol]);
            float e3 = __expf(c[nt][3] + bias[ncol + 1]);
            *(float2*)&out[GEN_OFF + (size_t)row_lo * EXT + ncol] = make_float2(e0, e1);
            *(float2*)&out[GEN_OFF + (size_t)row_hi * EXT + ncol] = make_float2(e2, e3);
            sum_lo += e0 + e1;
            sum_hi += e2 + e3;
        } else if (ncol < VOCAB) {
            float e0 = __expf(c[nt][0] + bias[ncol]);
            float e2 = __expf(c[nt][2] + bias[ncol]);
            out[GEN_OFF + (size_t)row_lo * EXT + ncol] = e0;
            out[GEN_OFF + (size_t)row_hi * EXT + ncol] = e2;
            sum_lo += e0;
            sum_hi += e2;
        }
    }
    atomicAdd(&red[row_lo], sum_lo);
    atomicAdd(&red[row_hi], sum_hi);
    __syncthreads();
    if (tid < 64) atomicAdd(&g_expsum[tid], red[tid]);
}

__global__ void normalize_kernel(float* __restrict__ out) {
    int idx = blockIdx.x * blockDim.x + threadIdx.x;
    if (idx >= B * EXT) return;
    int b = idx / EXT;
    int v = idx - b * EXT;
    float* p = out + GEN_OFF + idx;
    *p = (v < VOCAB) ? (*p) * (1.f / g_expsum[b]) : 0.f;
}

// ---------------- GRU gate ----------------
__global__ void gru_gate_kernel(const float* __restrict__ hprev, float* __restrict__ out) {
    int idx = blockIdx.x * blockDim.x + threadIdx.x;
    if (idx >= B * UNITS) return;
    int b = idx >> 9, u = idx & 511;
    const float* xm = g_xm + b * (3 * UNITS);
    const float* hm = g_hm + b * (3 * UNITS);
    float z  = 1.f / (1.f + __expf(-(xm[u] + hm[u])));
    float r  = 1.f / (1.f + __expf(-(xm[UNITS + u] + hm[UNITS + u])));
    float hc = tanhf(xm[2 * UNITS + u] + r * hm[2 * UNITS + u]);
    float h  = hprev[idx];
    float hn = z * h + (1.f - z) * hc;
    out[DEC_OFF + idx] = hn;
    g_xcat[b * (2 * UNITS) + UNITS + u] = hn;
}

// ---------------- sentence attention ----------------
__global__ __launch_bounds__(512) void attn_sent_kernel(const float* __restrict__ encS) {
    __shared__ float q_s[UNITS];
    __shared__ float sc_s[NSENT];
    __shared__ float alpha_s[NSENT];
    int b = blockIdx.x, tid = threadIdx.x;
    int warp = tid >> 5, lane = tid & 31;

    q_s[tid] = g_q[b * UNITS + tid];
    __syncthreads();
#pragma unroll
    for (int i = 0; i < 2; i++) {
        int s = warp * 2 + i;
        const float4* row = (const float4*)(encS + ((size_t)(b * NSENT + s)) * UNITS);
        const float4* qv  = (const float4*)q_s;
        float acc = 0.f;
#pragma unroll
        for (int t = 0; t < 4; t++) {
            float4 e = row[lane + t * 32], qq = qv[lane + t * 32];
            acc += e.x*qq.x + e.y*qq.y + e.z*qq.z + e.w*qq.w;
        }
#pragma unroll
        for (int o = 16; o > 0; o >>= 1) acc += __shfl_down_sync(0xffffffffu, acc, o);
        if (lane == 0) sc_s[s] = acc;
    }
    __syncthreads();
    if (warp == 0) {
        float x = sc_s[lane], m = x;
#pragma unroll
        for (int o = 16; o > 0; o >>= 1) m = fmaxf(m, __shfl_xor_sync(0xffffffffu, m, o));
        float e = __expf(x - m), s = e;
#pragma unroll
        for (int o = 16; o > 0; o >>= 1) s += __shfl_xor_sync(0xffffffffu, s, o);
        float a = e / s;
        alpha_s[lane] = a;
        g_alpha[b * NSENT + lane] = a;
    }
    __syncthreads();
    {
        float c = 0.f;
#pragma unroll
        for (int s = 0; s < NSENT; s++)
            c += alpha_s[s] * encS[((size_t)(b * NSENT + s)) * UNITS + tid];
        g_xcat[b * (2 * UNITS) + tid] = c;
    }
}

// ---------------- word attention + scatter + fused pgen ----------------
__global__ __launch_bounds__(256) void word_attn_scatter_kernel(
    const float* __restrict__ encW, const int* __restrict__ numeric,
    const float* __restrict__ emb, const float* __restrict__ wc,
    const float* __restrict__ wh, const float* __restrict__ wi,
    float* __restrict__ out)
{
    __shared__ float qw_s[UNITS];
    __shared__ float sc_s[NWORD];
    __shared__ float ms_s[2];
    int bid = blockIdx.x;
    int tid = threadIdx.x, warp = tid >> 5, lane = tid & 31;

    if (bid >= B * NSENT) {
        int b = bid - B * NSENT;
        const float* ctx = g_xcat + b * (2 * UNITS);
        const float* dec = ctx + UNITS;
        float acc = 0.f;
        for (int k = tid; k < UNITS; k += 256) {
            acc += ctx[k] * wc[k] + dec[k] * wh[k];
            if (k < EMB) acc += emb[b * EMB + k] * wi[k];
        }
        qw_s[tid] = acc;
        __syncthreads();
        for (int o = 128; o > 0; o >>= 1) {
            if (tid < o) qw_s[tid] += qw_s[tid + o];
            __syncthreads();
        }
        if (tid == 0) out[PGEN_OFF + b] = 1.f / (1.f + __expf(-qw_s[0]));
        return;
    }

    int b = bid >> 5, s = bid & 31;
    for (int u = tid; u < UNITS; u += 256) qw_s[u] = g_qw[b * UNITS + u];
    __syncthreads();
    const float* base = encW + ((size_t)(b * NSENT + s)) * NWORD * UNITS;
    for (int w = warp; w < NWORD; w += 8) {
        const float4* row = (const float4*)(base + (size_t)w * UNITS);
        const float4* qv  = (const float4*)qw_s;
        float acc = 0.f;
#pragma unroll
        for (int t = 0; t < 4; t++) {
            float4 e = __ldcs(&row[lane + t * 32]);
            float4 qq = qv[lane + t * 32];
            acc += e.x*qq.x + e.y*qq.y + e.z*qq.z + e.w*qq.w;
        }
#pragma unroll
        for (int o = 16; o > 0; o >>= 1) acc += __shfl_down_sync(0xffffffffu, acc, o);
        if (lane == 0) sc_s[w] = acc;
    }
    __syncthreads();
    if (warp == 0) {
        float m = -1e30f;
        for (int i = lane; i < NWORD; i += 32) m = fmaxf(m, sc_s[i]);
#pragma unroll
        for (int o = 16; o > 0; o >>= 1) m = fmaxf(m, __shfl_xor_sync(0xffffffffu, m, o));
        float ssum = 0.f;
        for (int i = lane; i < NWORD; i += 32) ssum += __expf(sc_s[i] - m);
#pragma unroll
        for (int o = 16; o > 0; o >>= 1) ssum += __shfl_xor_sync(0xffffffffu, ssum, o);
        if (lane == 0) { ms_s[0] = m; ms_s[1] = ssum; }
    }
    __syncthreads();
    if (tid < NWORD) {
        float alpha = g_alpha[b * NSENT + s];
        float v = alpha * __expf(sc_s[tid] - ms_s[0]) / ms_s[1];
        int col = numeric[b * (NSENT * NWORD) + s * NWORD + tid];
        atomicAdd(&out[COPY_OFF + (size_t)b * EXT + col], v);
    }
}

// ---------------- launch ----------------
extern "C" void kernel_launch(void* const* d_in, const int* in_sizes, int n_in,
                              void* d_out, int out_size)
{
    const float* emb   = (const float*)d_in[0];
    const float* hid   = (const float*)d_in[1];
    const float* encS  = (const float*)d_in[2];
    const float* encW  = (const float*)d_in[3];
    const int*   numr  = (const int*)d_in[4];
    int o = (in_sizes[5] == 1) ? 6 : 5;
    const float* gruWx = (const float*)d_in[o + 0];
    const float* gruWh = (const float*)d_in[o + 1];
    const float* grub  = (const float*)d_in[o + 2];
    const float* WatS  = (const float*)d_in[o + 3];
    const float* WatW  = (const float*)d_in[o + 4];
    const float* fcW   = (const float*)d_in[o + 5];
    const float* fcb   = (const float*)d_in[o + 6];
    const float* wctx  = (const float*)d_in[o + 7];
    const float* whid  = (const float*)d_in[o + 8];
    const float* wdec  = (const float*)d_in[o + 9];
    const float* winp  = (const float*)d_in[o + 10];

    float* out = (float*)d_out;

    float *xm, *hm, *q, *qw, *xcat;
    cudaGetSymbolAddress((void**)&xm, g_xm);
    cudaGetSymbolAddress((void**)&hm, g_hm);
    cudaGetSymbolAddress((void**)&q,  g_q);
    cudaGetSymbolAddress((void**)&qw, g_qw);
    cudaGetSymbolAddress((void**)&xcat, g_xcat);

    static cudaStream_t s1 = nullptr;
    static cudaEvent_t ev_fork = nullptr, ev_alpha = nullptr, ev_join = nullptr;
    if (!s1) {
        cudaStreamCreateWithFlags(&s1, cudaStreamNonBlocking);
        cudaEventCreateWithFlags(&ev_fork,  cudaEventDisableTiming);
        cudaEventCreateWithFlags(&ev_alpha, cudaEventDisableTiming);
        cudaEventCreateWithFlags(&ev_join,  cudaEventDisableTiming);
        cudaFuncSetAttribute(fc_gemm_kernel,
                             cudaFuncAttributeMaxDynamicSharedMemorySize, FC_SMEM);
    }

    // fork: side stream zeroes copy region while main chain runs
    cudaEventRecord(ev_fork, 0);
    cudaStreamWaitEvent(s1, ev_fork, 0);
    cudaMemsetAsync(out + COPY_OFF, 0, (size_t)B * EXT * sizeof(float), s1);

    // main: GRU pre-activations (fused, pipelined) -> gate -> queries -> sentence attention
    gemm_dual_kernel<<<96, 256>>>(
        emb, EMB, gruWx, 3*UNITS, grub,           xm, 3*UNITS, EMB, 48,
        hid, UNITS, gruWh, 3*UNITS, grub+3*UNITS, hm, 3*UNITS, UNITS);
    gru_gate_kernel<<<(B*UNITS + 255)/256, 256>>>(hid, out);
    gemm_dual_kernel<<<32, 256>>>(
        out + DEC_OFF, UNITS, WatS, UNITS, nullptr, q,  UNITS, UNITS, 16,
        out + DEC_OFF, UNITS, WatW, UNITS, nullptr, qw, UNITS, UNITS);
    attn_sent_kernel<<<B, 512>>>(encS);
    cudaEventRecord(ev_alpha, 0);

    // side: word attention + scatter + pgen (fused)
    cudaStreamWaitEvent(s1, ev_alpha, 0);
    word_attn_scatter_kernel<<<B * NSENT + B, 256, 0, s1>>>(
        encW, numr, emb, wctx, whid, winp, out);
    cudaEventRecord(ev_join, s1);

    // main: hidden (split-K partials) -> tanh+sum (+expsum zero) -> fc -> normalize
    gemm_splitk_kernel<<<dim3(8, 8), 256>>>(xcat, 2*UNITS, wdec, UNITS/2, 128);
    tanh_kernel<<<(HID_N + 255)/256, 256>>>();
    fc_gemm_kernel<<<(VOCAB + 127)/128, 256, FC_SMEM>>>(fcW, fcb, out);
    normalize_kernel<<<(B*EXT + 255)/256, 256>>>(out);

    cudaStreamWaitEvent(0, ev_join, 0);
}